// round 15
// baseline (speedup 1.0000x reference)
#include <cuda_runtime.h>
#include <cuda_bf16.h>
#include <cstdint>

// Problem constants
#define BDIM      2048
#define T_IN      48
#define FEAT      64
#define UNITS     1024
#define G4        4096
#define OUT_STEPS 64

#define NCHW 17          // warmup base K chunks: (64 + 1024)/64
#define NCHD 16          // decode base K chunks: 1024/64
#define MT   128         // M tile (batch rows per CTA)
#define NT   256         // N tile (gate cols per CTA) = 64 units
#define NTHR 512
#define STAGES 3
#define STAGE_BYTES 49152          // 16KB A + 32KB B
#define SMEM_TOTAL (STAGES * STAGE_BYTES)   // 147456; also covers epilogue stage 133KB

// ---------------------------------------------------------------------------
// Persistent scratch (__device__ globals; no allocations allowed)
// ---------------------------------------------------------------------------
__device__ float          g_c   [BDIM * UNITS];            // cell state fp32 [batch][unit]
__device__ float          g_hf  [2][BDIM * UNITS];         // h fp32 (for pred)
__device__ __nv_bfloat16  g_hhi [2][BDIM * UNITS];         // h hi bf16 [batch][unit]
__device__ __nv_bfloat16  g_hlo [2][BDIM * UNITS];         // h lo bf16
__device__ __nv_bfloat16  g_xhi [BDIM * T_IN * FEAT];      // x split [batch][t*64+f]
__device__ __nv_bfloat16  g_xlo [BDIM * T_IN * FEAT];
__device__ float          g_Ueff[UNITS * G4];              // U + Wd@W (gate-blocked)
__device__ float          g_beff[G4];                      // b + bd@W
// Pre-swizzled, gate-interleaved (col' = 4u+g), chunk-tiled B (SW128, [n][k]):
__device__ __nv_bfloat16  g_Bw_hi[NCHW * G4 * 64];
__device__ __nv_bfloat16  g_Bw_lo[NCHW * G4 * 64];
__device__ __nv_bfloat16  g_Bd_hi[NCHD * G4 * 64];
__device__ __nv_bfloat16  g_Bd_lo[NCHD * G4 * 64];

// ---------------------------------------------------------------------------
// Helpers
// ---------------------------------------------------------------------------
__device__ __forceinline__ float sigf(float x) { return 1.0f / (1.0f + __expf(-x)); }
__device__ __forceinline__ float tanh_(float x) { return 2.0f * sigf(2.0f * x) - 1.0f; }

__device__ __forceinline__ uint32_t swz(uint32_t o) { return o ^ ((o >> 3) & 0x70); }

__device__ __forceinline__ uint32_t smem_u32(const void* p) {
    uint32_t a;
    asm("{ .reg .u64 t; cvta.to.shared.u64 t, %1; cvt.u32.u64 %0, t; }" : "=r"(a) : "l"(p));
    return a;
}
__device__ __forceinline__ void cp_async16(uint32_t dst, const void* src) {
    asm volatile("cp.async.cg.shared.global [%0], [%1], 16;"
                 :: "r"(dst), "l"(__cvta_generic_to_global(src)) : "memory");
}

#define LDSM4(r, addr) \
    asm volatile("ldmatrix.sync.aligned.m8n8.x4.shared.b16 {%0,%1,%2,%3}, [%4];" \
                 : "=r"((r)[0]), "=r"((r)[1]), "=r"((r)[2]), "=r"((r)[3]) : "r"(addr))

#define MMA16816(d, a, b) \
    asm volatile("mma.sync.aligned.m16n8k16.row.col.f32.bf16.bf16.f32 " \
                 "{%0,%1,%2,%3},{%4,%5,%6,%7},{%8,%9},{%0,%1,%2,%3};" \
                 : "+f"((d)[0]), "+f"((d)[1]), "+f"((d)[2]), "+f"((d)[3]) \
                 : "r"((a)[0]), "r"((a)[1]), "r"((a)[2]), "r"((a)[3]), \
                   "r"((b)[0]), "r"((b)[1]))

// ---------------------------------------------------------------------------
// Prologue kernels (merged so ncu -s 5 lands on cell_mma)
// ---------------------------------------------------------------------------
__global__ void init_split(const float* __restrict__ in) {
    int n1 = BDIM * UNITS;
    for (int i = blockIdx.x * blockDim.x + threadIdx.x; i < n1; i += gridDim.x * blockDim.x) {
        g_c[i] = 0.0f;
        g_hhi[0][i] = __float2bfloat16(0.0f);
        g_hlo[0][i] = __float2bfloat16(0.0f);
    }
    int n2 = BDIM * T_IN * FEAT;
    for (int i = blockIdx.x * blockDim.x + threadIdx.x; i < n2; i += gridDim.x * blockDim.x) {
        float v = in[i];
        __nv_bfloat16 hi = __float2bfloat16(v);
        g_xhi[i] = hi;
        g_xlo[i] = __float2bfloat16(v - __bfloat162float(hi));
    }
}

__global__ void prep_ueff(const float* __restrict__ U, const float* __restrict__ Wd,
                          const float* __restrict__ W) {
    __shared__ float wd[FEAT];
    int u = blockIdx.x;
    if (threadIdx.x < FEAT) wd[threadIdx.x] = Wd[u * FEAT + threadIdx.x];
    __syncthreads();
    for (int j = threadIdx.x; j < G4; j += blockDim.x) {
        float acc = U[(size_t)u * G4 + j];
#pragma unroll 16
        for (int k = 0; k < FEAT; k++) acc += wd[k] * W[(size_t)k * G4 + j];
        g_Ueff[(size_t)u * G4 + j] = acc;
    }
}

__global__ void prep_beff(const float* __restrict__ b, const float* __restrict__ bd,
                          const float* __restrict__ W) {
    int j = blockIdx.x * blockDim.x + threadIdx.x;
    if (j < G4) {
        float acc = b[j];
#pragma unroll 16
        for (int k = 0; k < FEAT; k++) acc += bd[k] * W[(size_t)k * G4 + j];
        g_beff[j] = acc;
    }
}

// Build BOTH B operand sets (chunk-tiled [n][k64], col'=4u+g, SW128-pre-swizzled)
__global__ void build_B(const float* __restrict__ W, const float* __restrict__ U) {
    int totalw = NCHW * 64 * G4;
    for (int idx = blockIdx.x * blockDim.x + threadIdx.x; idx < totalw;
         idx += gridDim.x * blockDim.x) {
        int kp = idx >> 12, n = idx & 4095;       // kp in [0,1088)
        int g = n & 3, u = n >> 2;
        int j = g * UNITS + u;
        float v = (kp < FEAT) ? W[(size_t)kp * G4 + j] : U[(size_t)(kp - FEAT) * G4 + j];
        __nv_bfloat16 hi = __float2bfloat16(v);
        __nv_bfloat16 lo = __float2bfloat16(v - __bfloat162float(hi));
        int kc = kp >> 6, kl = kp & 63;
        size_t off = (size_t)kc * (G4 * 64) + (swz((uint32_t)n * 128 + kl * 2) >> 1);
        g_Bw_hi[off] = hi;
        g_Bw_lo[off] = lo;
    }
    int totald = NCHD * 64 * G4;
    for (int idx = blockIdx.x * blockDim.x + threadIdx.x; idx < totald;
         idx += gridDim.x * blockDim.x) {
        int kp = idx >> 12, n = idx & 4095;       // kp in [0,1024)
        int g = n & 3, u = n >> 2;
        float v = g_Ueff[(size_t)kp * G4 + g * UNITS + u];
        __nv_bfloat16 hi = __float2bfloat16(v);
        __nv_bfloat16 lo = __float2bfloat16(v - __bfloat162float(hi));
        int kc = kp >> 6, kl = kp & 63;
        size_t off = (size_t)kc * (G4 * 64) + (swz((uint32_t)n * 128 + kl * 2) >> 1);
        g_Bd_hi[off] = hi;
        g_Bd_lo[off] = lo;
    }
}

// ---------------------------------------------------------------------------
// mma.sync fused LSTM cell step.
// Z = [Ahi|Ahi|Alo] @ [Bhi;Blo;Bhi]  (bf16 split, fp32 register accum)
// CTA tile: M=128 x N=256 gate cols (64 units, col'=4u+gate), 512 threads.
// 16 warps (4m x 4n), warp tile 32x64, m16n8k16 HMMA, 3-stage cp.async.
// ---------------------------------------------------------------------------
template <bool WARMUP>
__global__ void __launch_bounds__(NTHR, 1) cell_mma(int step, int cur,
                                                    const float* __restrict__ bias_in) {
    extern __shared__ char smem[];
    const uint32_t sb = smem_u32(smem);
    float* stage = reinterpret_cast<float*>(smem);
    const int tid = threadIdx.x;
    const int m0 = blockIdx.y * MT;
    const int n0 = blockIdx.x * NT;
    const int ubase = blockIdx.x * (NT / 4);
    const int NCH = WARMUP ? NCHW : NCHD;
    const int TOTAL = 3 * NCH;

    const __nv_bfloat16* __restrict__ hhi = g_hhi[cur];
    const __nv_bfloat16* __restrict__ hlo = g_hlo[cur];

    auto issue_chunk = [&](int c) {
        int slot = c % STAGES;
        int term = c / NCH;
        int kc = c - term * NCH;
        const __nv_bfloat16* Asrc;
        int astride, aoffk;
        if (WARMUP && kc == 0) {
            Asrc = (term < 2) ? g_xhi : g_xlo;
            astride = T_IN * FEAT;
            aoffk = step * FEAT;
        } else {
            Asrc = (term < 2) ? hhi : hlo;
            astride = UNITS;
            aoffk = (WARMUP ? (kc - 1) : kc) * 64;
        }
        const __nv_bfloat16* Bsrc = WARMUP ? ((term == 1) ? g_Bw_lo : g_Bw_hi)
                                           : ((term == 1) ? g_Bd_lo : g_Bd_hi);
        const uint32_t abase = sb + slot * STAGE_BYTES;
        const uint32_t bbase = abase + 16384;
        // A tile: 128 rows x 64 bf16, SW128 swizzle on 16B units
#pragma unroll
        for (int i = 0; i < 2; i++) {
            int f = tid + i * NTHR;
            int r = f >> 3, q = f & 7;
            uint32_t dst = abase + r * 128 + ((q * 16) ^ ((r & 7) * 16));
            cp_async16(dst, Asrc + (size_t)(m0 + r) * astride + aoffk + q * 8);
        }
        // B tile: 256 n-rows x 64 bf16, pre-swizzled global -> straight copy
        const __nv_bfloat16* bchunk = Bsrc + (size_t)kc * (G4 * 64) + (size_t)n0 * 64;
#pragma unroll
        for (int i = 0; i < 4; i++) {
            int f = tid + i * NTHR;
            cp_async16(bbase + f * 16, bchunk + f * 8);
        }
        asm volatile("cp.async.commit_group;" ::: "memory");
    };

    float acc[2][8][4];
#pragma unroll
    for (int mt = 0; mt < 2; mt++)
#pragma unroll
        for (int nt = 0; nt < 8; nt++)
#pragma unroll
            for (int e = 0; e < 4; e++) acc[mt][nt][e] = 0.0f;

    const int lane = tid & 31, warp = tid >> 5;
    const int wm = warp >> 2, wn = warp & 3;      // 4 x 4 warp grid
    const int lrow = lane & 15;
    const int lk = (lane >> 4) * 16;              // upper-k byte offset for x4

    issue_chunk(0);
    if (TOTAL > 1) issue_chunk(1);
    for (int c = 0; c < TOTAL; c++) {
        if (c + 2 < TOTAL) {
            issue_chunk(c + 2);
            asm volatile("cp.async.wait_group 2;" ::: "memory");
        } else {
            asm volatile("cp.async.wait_group 0;" ::: "memory");
        }
        __syncthreads();
        const uint32_t Abase = sb + (c % STAGES) * STAGE_BYTES;
        const uint32_t Bbase = Abase + 16384;
#pragma unroll
        for (int ks = 0; ks < 4; ks++) {
            const int kb = ks * 32 + lk;
            uint32_t a[2][4];
#pragma unroll
            for (int mt = 0; mt < 2; mt++) {
                int row = wm * 32 + mt * 16 + lrow;
                LDSM4(a[mt], Abase + row * 128 + (kb ^ ((row & 7) * 16)));
            }
            uint32_t b[8][2];
#pragma unroll
            for (int np = 0; np < 4; np++) {
                int nrow = wn * 64 + np * 16 + lrow;
                uint32_t r[4];
                LDSM4(r, Bbase + nrow * 128 + (kb ^ ((nrow & 7) * 16)));
                b[np * 2][0] = r[0];
                b[np * 2 + 1][0] = r[1];
                b[np * 2][1] = r[2];
                b[np * 2 + 1][1] = r[3];
            }
#pragma unroll
            for (int mt = 0; mt < 2; mt++)
#pragma unroll
                for (int nt = 0; nt < 8; nt++) MMA16816(acc[mt][nt], a[mt], b[nt]);
        }
        __syncthreads();
    }

    // ---- Epilogue: frags -> stage (stride 260 floats, conflict-free) ----
    const int S = 260;
    const int g = lane >> 2, tg = lane & 3;
#pragma unroll
    for (int mt = 0; mt < 2; mt++)
#pragma unroll
        for (int nt = 0; nt < 8; nt++) {
            int row = wm * 32 + mt * 16 + g;
            int col = wn * 64 + nt * 8 + 2 * tg;
            *reinterpret_cast<float2*>(&stage[row * S + col]) =
                make_float2(acc[mt][nt][0], acc[mt][nt][1]);
            *reinterpret_cast<float2*>(&stage[(row + 8) * S + col]) =
                make_float2(acc[mt][nt][2], acc[mt][nt][3]);
        }
    __syncthreads();

    // gates + state update: thread -> unit (tid&63), rows (tid>>6) + 8*it
    const float* __restrict__ bias = WARMUP ? bias_in : g_beff;
    float* __restrict__ hf = g_hf[cur ^ 1];
    __nv_bfloat16* __restrict__ ohi = g_hhi[cur ^ 1];
    __nv_bfloat16* __restrict__ olo = g_hlo[cur ^ 1];

    const int u = tid & 63;
    const int unit = ubase + u;
    const float bi = bias[unit], bff = bias[UNITS + unit];
    const float bg = bias[2 * UNITS + unit], bo = bias[3 * UNITS + unit];
#pragma unroll 4
    for (int it = 0; it < 16; it++) {
        int r = (tid >> 6) + it * 8;
        float4 z = *reinterpret_cast<const float4*>(&stage[r * S + 4 * u]);
        size_t idx = (size_t)(m0 + r) * UNITS + unit;
        float cold = g_c[idx];
        float cn = sigf(z.y + bff) * cold + sigf(z.x + bi) * tanh_(z.z + bg);
        float hn = sigf(z.w + bo) * tanh_(cn);
        g_c[idx] = cn;
        hf[idx] = hn;
        __nv_bfloat16 hb = __float2bfloat16(hn);
        ohi[idx] = hb;
        olo[idx] = __float2bfloat16(hn - __bfloat162float(hb));
    }
}

// ---------------------------------------------------------------------------
// Prediction: out[:, t, :] = h @ Wd + bd.  h fp32 natural [batch][unit].
// ---------------------------------------------------------------------------
__global__ void __launch_bounds__(256) pred_kernel(float* __restrict__ out, int t, int cur,
                                                   const float* __restrict__ Wd,
                                                   const float* __restrict__ bd) {
    __shared__ __align__(16) float As[64][68];
    __shared__ __align__(16) float Bs[64][FEAT];
    const float* __restrict__ h = g_hf[cur];
    const int tid = threadIdx.x;
    const int tx = tid & 15, ty = tid >> 4;
    const int row0 = blockIdx.x * 64;

    float acc[4][4] = {};
    for (int k0 = 0; k0 < UNITS; k0 += 64) {
#pragma unroll
        for (int i = 0; i < 4; i++) {
            int f = tid + i * 256;
            int r = f >> 4, q = f & 15;
            *reinterpret_cast<float4*>(&As[r][q * 4]) =
                *reinterpret_cast<const float4*>(&h[(size_t)(row0 + r) * UNITS + k0 + q * 4]);
        }
#pragma unroll
        for (int i = 0; i < 4; i++) {
            int f = tid + i * 256;
            int k = f >> 4, q = f & 15;
            *reinterpret_cast<float4*>(&Bs[k][q * 4]) =
                *reinterpret_cast<const float4*>(&Wd[(size_t)(k0 + k) * FEAT + q * 4]);
        }
        __syncthreads();
#pragma unroll 8
        for (int k = 0; k < 64; k++) {
            float4 bv = *reinterpret_cast<const float4*>(&Bs[k][tx * 4]);
#pragma unroll
            for (int rr = 0; rr < 4; rr++) {
                float a = As[ty * 4 + rr][k];
                acc[rr][0] += a * bv.x;
                acc[rr][1] += a * bv.y;
                acc[rr][2] += a * bv.z;
                acc[rr][3] += a * bv.w;
            }
        }
        __syncthreads();
    }
    float4 bdv = *reinterpret_cast<const float4*>(&bd[tx * 4]);
#pragma unroll
    for (int rr = 0; rr < 4; rr++) {
        int row = row0 + ty * 4 + rr;
        float4 o = make_float4(acc[rr][0] + bdv.x, acc[rr][1] + bdv.y,
                               acc[rr][2] + bdv.z, acc[rr][3] + bdv.w);
        *reinterpret_cast<float4*>(&out[(size_t)row * (OUT_STEPS * FEAT) + t * FEAT + tx * 4]) = o;
    }
}

// ---------------------------------------------------------------------------
extern "C" void kernel_launch(void* const* d_in, const int* in_sizes, int n_in,
                              void* d_out, int out_size) {
    const float* inputs = (const float*)d_in[0];
    const float* W      = (const float*)d_in[1];
    const float* U      = (const float*)d_in[2];
    const float* b      = (const float*)d_in[3];
    const float* Wd     = (const float*)d_in[4];
    const float* bd     = (const float*)d_in[5];
    float* out = (float*)d_out;

    cudaFuncSetAttribute((const void*)cell_mma<true>,
                         cudaFuncAttributeMaxDynamicSharedMemorySize, SMEM_TOTAL);
    cudaFuncSetAttribute((const void*)cell_mma<false>,
                         cudaFuncAttributeMaxDynamicSharedMemorySize, SMEM_TOTAL);

    init_split<<<512, 256>>>(inputs);
    prep_ueff<<<UNITS, 256>>>(U, Wd, W);
    prep_beff<<<G4 / 256, 256>>>(b, bd, W);
    build_B<<<1024, 256>>>(W, U);

    dim3 grid(G4 / NT, BDIM / MT);  // 16 x 16 = 256 CTAs
    int cur = 0;

    for (int t = 0; t < T_IN; t++) {
        cell_mma<true><<<grid, NTHR, SMEM_TOTAL>>>(t, cur, b);
        cur ^= 1;
    }
    pred_kernel<<<BDIM / 64, 256>>>(out, 0, cur, Wd, bd);
    for (int t = 1; t < OUT_STEPS; t++) {
        cell_mma<false><<<grid, NTHR, SMEM_TOTAL>>>(0, cur, b);
        cur ^= 1;
        pred_kernel<<<BDIM / 64, 256>>>(out, t, cur, Wd, bd);
    }
}

// round 16
// speedup vs baseline: 1.0640x; 1.0640x over previous
#include <cuda_runtime.h>
#include <cuda_bf16.h>
#include <cstdint>

// Problem constants
#define BDIM      2048
#define T_IN      48
#define FEAT      64
#define UNITS     1024
#define G4        4096
#define OUT_STEPS 64

#define NCHW 17          // warmup base K chunks: (64 + 1024)/64
#define NCHD 16          // decode base K chunks: 1024/64
#define MT   128         // M tile (batch rows per CTA)
#define NT   128         // N tile (gate cols per CTA) = 32 units
#define NTHR 256
#define STAGES 3
#define STAGE_BYTES 32768              // 16KB A + 16KB B
#define SMEM_TOTAL (STAGES * STAGE_BYTES)  // 98304; epilogue stage 67.5KB fits

// ---------------------------------------------------------------------------
// Persistent scratch (__device__ globals; no allocations allowed)
// ---------------------------------------------------------------------------
__device__ float          g_c   [BDIM * UNITS];            // cell state fp32 [batch][unit]
__device__ float          g_hf  [2][BDIM * UNITS];         // h fp32 (for pred)
__device__ __nv_bfloat16  g_hhi [2][BDIM * UNITS];         // h hi bf16 [batch][unit]
__device__ __nv_bfloat16  g_hlo [2][BDIM * UNITS];         // h lo bf16
__device__ __nv_bfloat16  g_xhi [BDIM * T_IN * FEAT];      // x split [batch][t*64+f]
__device__ __nv_bfloat16  g_xlo [BDIM * T_IN * FEAT];
__device__ float          g_Ueff[UNITS * G4];              // U + Wd@W (gate-blocked)
__device__ float          g_beff[G4];                      // b + bd@W
// Pre-swizzled, gate-interleaved (col' = 4u+g), chunk-tiled B (SW128, [n][k]):
__device__ __nv_bfloat16  g_Bw_hi[NCHW * G4 * 64];
__device__ __nv_bfloat16  g_Bw_lo[NCHW * G4 * 64];
__device__ __nv_bfloat16  g_Bd_hi[NCHD * G4 * 64];
__device__ __nv_bfloat16  g_Bd_lo[NCHD * G4 * 64];

// ---------------------------------------------------------------------------
// Helpers
// ---------------------------------------------------------------------------
__device__ __forceinline__ float sigf(float x) { return 1.0f / (1.0f + __expf(-x)); }
__device__ __forceinline__ float tanh_(float x) { return 2.0f * sigf(2.0f * x) - 1.0f; }

__device__ __forceinline__ uint32_t swz(uint32_t o) { return o ^ ((o >> 3) & 0x70); }

__device__ __forceinline__ uint32_t smem_u32(const void* p) {
    uint32_t a;
    asm("{ .reg .u64 t; cvta.to.shared.u64 t, %1; cvt.u32.u64 %0, t; }" : "=r"(a) : "l"(p));
    return a;
}
__device__ __forceinline__ void cp_async16(uint32_t dst, const void* src) {
    asm volatile("cp.async.cg.shared.global [%0], [%1], 16;"
                 :: "r"(dst), "l"(__cvta_generic_to_global(src)) : "memory");
}

#define LDSM4(r, addr) \
    asm volatile("ldmatrix.sync.aligned.m8n8.x4.shared.b16 {%0,%1,%2,%3}, [%4];" \
                 : "=r"((r)[0]), "=r"((r)[1]), "=r"((r)[2]), "=r"((r)[3]) : "r"(addr))

#define MMA16816(d, a, b) \
    asm volatile("mma.sync.aligned.m16n8k16.row.col.f32.bf16.bf16.f32 " \
                 "{%0,%1,%2,%3},{%4,%5,%6,%7},{%8,%9},{%0,%1,%2,%3};" \
                 : "+f"((d)[0]), "+f"((d)[1]), "+f"((d)[2]), "+f"((d)[3]) \
                 : "r"((a)[0]), "r"((a)[1]), "r"((a)[2]), "r"((a)[3]), \
                   "r"((b)[0]), "r"((b)[1]))

// ---------------------------------------------------------------------------
// Prologue kernels (3 launches total so ncu -s 5 lands on cell_mma)
// ---------------------------------------------------------------------------
__global__ void init_split(const float* __restrict__ in) {
    int n1 = BDIM * UNITS;
    for (int i = blockIdx.x * blockDim.x + threadIdx.x; i < n1; i += gridDim.x * blockDim.x) {
        g_c[i] = 0.0f;
        g_hhi[0][i] = __float2bfloat16(0.0f);
        g_hlo[0][i] = __float2bfloat16(0.0f);
    }
    int n2 = BDIM * T_IN * FEAT;
    for (int i = blockIdx.x * blockDim.x + threadIdx.x; i < n2; i += gridDim.x * blockDim.x) {
        float v = in[i];
        __nv_bfloat16 hi = __float2bfloat16(v);
        g_xhi[i] = hi;
        g_xlo[i] = __float2bfloat16(v - __bfloat162float(hi));
    }
}

// Ueff = U + Wd@W (1024 blocks, one per unit row); blocks 0..15 also do beff.
__global__ void prep_ue_be(const float* __restrict__ U, const float* __restrict__ Wd,
                           const float* __restrict__ W, const float* __restrict__ b,
                           const float* __restrict__ bd) {
    __shared__ float wd[FEAT];
    int u = blockIdx.x;
    if (threadIdx.x < FEAT) wd[threadIdx.x] = Wd[u * FEAT + threadIdx.x];
    __syncthreads();
    for (int j = threadIdx.x; j < G4; j += blockDim.x) {
        float acc = U[(size_t)u * G4 + j];
#pragma unroll 16
        for (int k = 0; k < FEAT; k++) acc += wd[k] * W[(size_t)k * G4 + j];
        g_Ueff[(size_t)u * G4 + j] = acc;
    }
    if (blockIdx.x < 16) {
        int j = blockIdx.x * 256 + threadIdx.x;
        float acc = b[j];
#pragma unroll 16
        for (int k = 0; k < FEAT; k++) acc += bd[k] * W[(size_t)k * G4 + j];
        g_beff[j] = acc;
    }
}

// Build BOTH B operand sets (chunk-tiled [n][k64], col'=4u+g, SW128-pre-swizzled)
__global__ void build_B(const float* __restrict__ W, const float* __restrict__ U) {
    int totalw = NCHW * 64 * G4;
    for (int idx = blockIdx.x * blockDim.x + threadIdx.x; idx < totalw;
         idx += gridDim.x * blockDim.x) {
        int kp = idx >> 12, n = idx & 4095;       // kp in [0,1088)
        int g = n & 3, u = n >> 2;
        int j = g * UNITS + u;
        float v = (kp < FEAT) ? W[(size_t)kp * G4 + j] : U[(size_t)(kp - FEAT) * G4 + j];
        __nv_bfloat16 hi = __float2bfloat16(v);
        __nv_bfloat16 lo = __float2bfloat16(v - __bfloat162float(hi));
        int kc = kp >> 6, kl = kp & 63;
        size_t off = (size_t)kc * (G4 * 64) + (swz((uint32_t)n * 128 + kl * 2) >> 1);
        g_Bw_hi[off] = hi;
        g_Bw_lo[off] = lo;
    }
    int totald = NCHD * 64 * G4;
    for (int idx = blockIdx.x * blockDim.x + threadIdx.x; idx < totald;
         idx += gridDim.x * blockDim.x) {
        int kp = idx >> 12, n = idx & 4095;       // kp in [0,1024)
        int g = n & 3, u = n >> 2;
        float v = g_Ueff[(size_t)kp * G4 + g * UNITS + u];
        __nv_bfloat16 hi = __float2bfloat16(v);
        __nv_bfloat16 lo = __float2bfloat16(v - __bfloat162float(hi));
        int kc = kp >> 6, kl = kp & 63;
        size_t off = (size_t)kc * (G4 * 64) + (swz((uint32_t)n * 128 + kl * 2) >> 1);
        g_Bd_hi[off] = hi;
        g_Bd_lo[off] = lo;
    }
}

// ---------------------------------------------------------------------------
// mma.sync fused LSTM cell step (R12 warp structure + 3-stage pipeline).
// Z = [Ahi|Ahi|Alo] @ [Bhi;Blo;Bhi]  (bf16 split, fp32 register accum)
// CTA tile: M=128 x N=128 gate cols (32 units, col'=4u+gate), 256 threads.
// 8 warps (4m x 2n), warp tile 32x64, m16n8k16 HMMA, 3-stage cp.async, occ 2.
// ---------------------------------------------------------------------------
template <bool WARMUP>
__global__ void __launch_bounds__(NTHR, 2) cell_mma(int step, int cur,
                                                    const float* __restrict__ bias_in) {
    extern __shared__ char smem[];
    const uint32_t sb = smem_u32(smem);
    float* stage = reinterpret_cast<float*>(smem);
    const int tid = threadIdx.x;
    const int m0 = blockIdx.y * MT;
    const int n0 = blockIdx.x * NT;
    const int ubase = blockIdx.x * (NT / 4);
    const int NCH = WARMUP ? NCHW : NCHD;
    const int TOTAL = 3 * NCH;

    const __nv_bfloat16* __restrict__ hhi = g_hhi[cur];
    const __nv_bfloat16* __restrict__ hlo = g_hlo[cur];

    auto issue_chunk = [&](int c) {
        int slot = c % STAGES;
        int term = c / NCH;
        int kc = c - term * NCH;
        const __nv_bfloat16* Asrc;
        int astride, aoffk;
        if (WARMUP && kc == 0) {
            Asrc = (term < 2) ? g_xhi : g_xlo;
            astride = T_IN * FEAT;
            aoffk = step * FEAT;
        } else {
            Asrc = (term < 2) ? hhi : hlo;
            astride = UNITS;
            aoffk = (WARMUP ? (kc - 1) : kc) * 64;
        }
        const __nv_bfloat16* Bsrc = WARMUP ? ((term == 1) ? g_Bw_lo : g_Bw_hi)
                                           : ((term == 1) ? g_Bd_lo : g_Bd_hi);
        const uint32_t abase = sb + slot * STAGE_BYTES;
        const uint32_t bbase = abase + 16384;
        // A tile: 128 rows x 64 bf16, SW128 swizzle on 16B units
#pragma unroll
        for (int i = 0; i < 4; i++) {
            int f = tid + i * NTHR;
            int r = f >> 3, q = f & 7;
            uint32_t dst = abase + r * 128 + ((q * 16) ^ ((r & 7) * 16));
            cp_async16(dst, Asrc + (size_t)(m0 + r) * astride + aoffk + q * 8);
        }
        // B tile: 128 n-rows x 64 bf16, pre-swizzled global -> straight copy
        const __nv_bfloat16* bchunk = Bsrc + (size_t)kc * (G4 * 64) + (size_t)n0 * 64;
#pragma unroll
        for (int i = 0; i < 4; i++) {
            int f = tid + i * NTHR;
            cp_async16(bbase + f * 16, bchunk + f * 8);
        }
        asm volatile("cp.async.commit_group;" ::: "memory");
    };

    float acc[2][8][4];
#pragma unroll
    for (int mt = 0; mt < 2; mt++)
#pragma unroll
        for (int nt = 0; nt < 8; nt++)
#pragma unroll
            for (int e = 0; e < 4; e++) acc[mt][nt][e] = 0.0f;

    const int lane = tid & 31, warp = tid >> 5;
    const int wm = warp >> 1, wn = warp & 1;      // 4 x 2 warp grid
    const int lrow = lane & 15;
    const int lk = (lane >> 4) * 16;              // upper-k byte offset for x4

    issue_chunk(0);
    if (TOTAL > 1) issue_chunk(1);
    for (int c = 0; c < TOTAL; c++) {
        if (c + 2 < TOTAL) {
            issue_chunk(c + 2);
            asm volatile("cp.async.wait_group 2;" ::: "memory");
        } else {
            asm volatile("cp.async.wait_group 0;" ::: "memory");
        }
        __syncthreads();
        const uint32_t Abase = sb + (c % STAGES) * STAGE_BYTES;
        const uint32_t Bbase = Abase + 16384;
#pragma unroll
        for (int ks = 0; ks < 4; ks++) {
            const int kb = ks * 32 + lk;
            uint32_t a[2][4];
#pragma unroll
            for (int mt = 0; mt < 2; mt++) {
                int row = wm * 32 + mt * 16 + lrow;
                LDSM4(a[mt], Abase + row * 128 + (kb ^ ((row & 7) * 16)));
            }
            uint32_t b[8][2];
#pragma unroll
            for (int np = 0; np < 4; np++) {
                int nrow = wn * 64 + np * 16 + lrow;
                uint32_t r[4];
                LDSM4(r, Bbase + nrow * 128 + (kb ^ ((nrow & 7) * 16)));
                b[np * 2][0] = r[0];
                b[np * 2 + 1][0] = r[1];
                b[np * 2][1] = r[2];
                b[np * 2 + 1][1] = r[3];
            }
#pragma unroll
            for (int mt = 0; mt < 2; mt++)
#pragma unroll
                for (int nt = 0; nt < 8; nt++) MMA16816(acc[mt][nt], a[mt], b[nt]);
        }
        __syncthreads();
    }

    // ---- Epilogue: frags -> stage (stride 132 floats, conflict-free) ----
    const int S = 132;
    const int g = lane >> 2, tg = lane & 3;
#pragma unroll
    for (int mt = 0; mt < 2; mt++)
#pragma unroll
        for (int nt = 0; nt < 8; nt++) {
            int row = wm * 32 + mt * 16 + g;
            int col = wn * 64 + nt * 8 + 2 * tg;
            *reinterpret_cast<float2*>(&stage[row * S + col]) =
                make_float2(acc[mt][nt][0], acc[mt][nt][1]);
            *reinterpret_cast<float2*>(&stage[(row + 8) * S + col]) =
                make_float2(acc[mt][nt][2], acc[mt][nt][3]);
        }
    __syncthreads();

    // gates + state update: thread -> unit (tid&31), rows (tid>>5) + 8*it
    const float* __restrict__ bias = WARMUP ? bias_in : g_beff;
    float* __restrict__ hf = g_hf[cur ^ 1];
    __nv_bfloat16* __restrict__ ohi = g_hhi[cur ^ 1];
    __nv_bfloat16* __restrict__ olo = g_hlo[cur ^ 1];

    const int u = tid & 31;
    const int unit = ubase + u;
    const float bi = bias[unit], bff = bias[UNITS + unit];
    const float bg = bias[2 * UNITS + unit], bo = bias[3 * UNITS + unit];
#pragma unroll 4
    for (int it = 0; it < 16; it++) {
        int r = (tid >> 5) + it * 8;
        float4 z = *reinterpret_cast<const float4*>(&stage[r * S + 4 * u]);
        size_t idx = (size_t)(m0 + r) * UNITS + unit;
        float cold = g_c[idx];
        float cn = sigf(z.y + bff) * cold + sigf(z.x + bi) * tanh_(z.z + bg);
        float hn = sigf(z.w + bo) * tanh_(cn);
        g_c[idx] = cn;
        hf[idx] = hn;
        __nv_bfloat16 hb = __float2bfloat16(hn);
        ohi[idx] = hb;
        olo[idx] = __float2bfloat16(hn - __bfloat162float(hb));
    }
}

// ---------------------------------------------------------------------------
// Prediction: out[:, t, :] = h @ Wd + bd.  h fp32 natural [batch][unit].
// ---------------------------------------------------------------------------
__global__ void __launch_bounds__(256) pred_kernel(float* __restrict__ out, int t, int cur,
                                                   const float* __restrict__ Wd,
                                                   const float* __restrict__ bd) {
    __shared__ __align__(16) float As[64][68];
    __shared__ __align__(16) float Bs[64][FEAT];
    const float* __restrict__ h = g_hf[cur];
    const int tid = threadIdx.x;
    const int tx = tid & 15, ty = tid >> 4;
    const int row0 = blockIdx.x * 64;

    float acc[4][4] = {};
    for (int k0 = 0; k0 < UNITS; k0 += 64) {
#pragma unroll
        for (int i = 0; i < 4; i++) {
            int f = tid + i * 256;
            int r = f >> 4, q = f & 15;
            *reinterpret_cast<float4*>(&As[r][q * 4]) =
                *reinterpret_cast<const float4*>(&h[(size_t)(row0 + r) * UNITS + k0 + q * 4]);
        }
#pragma unroll
        for (int i = 0; i < 4; i++) {
            int f = tid + i * 256;
            int k = f >> 4, q = f & 15;
            *reinterpret_cast<float4*>(&Bs[k][q * 4]) =
                *reinterpret_cast<const float4*>(&Wd[(size_t)(k0 + k) * FEAT + q * 4]);
        }
        __syncthreads();
#pragma unroll 8
        for (int k = 0; k < 64; k++) {
            float4 bv = *reinterpret_cast<const float4*>(&Bs[k][tx * 4]);
#pragma unroll
            for (int rr = 0; rr < 4; rr++) {
                float a = As[ty * 4 + rr][k];
                acc[rr][0] += a * bv.x;
                acc[rr][1] += a * bv.y;
                acc[rr][2] += a * bv.z;
                acc[rr][3] += a * bv.w;
            }
        }
        __syncthreads();
    }
    float4 bdv = *reinterpret_cast<const float4*>(&bd[tx * 4]);
#pragma unroll
    for (int rr = 0; rr < 4; rr++) {
        int row = row0 + ty * 4 + rr;
        float4 o = make_float4(acc[rr][0] + bdv.x, acc[rr][1] + bdv.y,
                               acc[rr][2] + bdv.z, acc[rr][3] + bdv.w);
        *reinterpret_cast<float4*>(&out[(size_t)row * (OUT_STEPS * FEAT) + t * FEAT + tx * 4]) = o;
    }
}

// ---------------------------------------------------------------------------
extern "C" void kernel_launch(void* const* d_in, const int* in_sizes, int n_in,
                              void* d_out, int out_size) {
    const float* inputs = (const float*)d_in[0];
    const float* W      = (const float*)d_in[1];
    const float* U      = (const float*)d_in[2];
    const float* b      = (const float*)d_in[3];
    const float* Wd     = (const float*)d_in[4];
    const float* bd     = (const float*)d_in[5];
    float* out = (float*)d_out;

    cudaFuncSetAttribute((const void*)cell_mma<true>,
                         cudaFuncAttributeMaxDynamicSharedMemorySize, SMEM_TOTAL);
    cudaFuncSetAttribute((const void*)cell_mma<false>,
                         cudaFuncAttributeMaxDynamicSharedMemorySize, SMEM_TOTAL);

    init_split<<<512, 256>>>(inputs);
    prep_ue_be<<<UNITS, 256>>>(U, Wd, W, b, bd);
    build_B<<<1024, 256>>>(W, U);

    dim3 grid(G4 / NT, BDIM / MT);  // 32 x 16 = 512 CTAs
    int cur = 0;

    for (int t = 0; t < T_IN; t++) {
        cell_mma<true><<<grid, NTHR, SMEM_TOTAL>>>(t, cur, b);
        cur ^= 1;
    }
    pred_kernel<<<BDIM / 64, 256>>>(out, 0, cur, Wd, bd);
    for (int t = 1; t < OUT_STEPS; t++) {
        cell_mma<false><<<grid, NTHR, SMEM_TOTAL>>>(0, cur, b);
        cur ^= 1;
        pred_kernel<<<BDIM / 64, 256>>>(out, t, cur, Wd, bd);
    }
}